// round 7
// baseline (speedup 1.0000x reference)
#include <cuda_runtime.h>
#include <cuda_bf16.h>

// Problem constants (from reference): B=32, T=1024, F=4, C=256, S=256, MAX_DUR=8
#define BQ 32
#define TQ 1024
#define FQ 4
#define CQ 256
#define SQ 256

// Scratch: inclusive cumsum of durations per batch. 32*256*4B = 32 KB.
__device__ int g_cum[BQ][SQ];

// ---------------------------------------------------------------------------
// Kernel 1: per-batch inclusive scan of durations (one block per batch).
// Dtype handling: reference declares jnp.int64 but JAX without x64 downcasts
// to int32; metadata is not visible here, so detect on device. Under the
// int64 hypothesis every high 32-bit word is zero (durations in [0,8));
// with int32 data the 32 probed words are random in [0,8):
// P(false positive) = 8^-32 ~ 0. Deterministic for fixed input bytes.
//
// Scan: warp-scan + warp-totals scan (8 warps of 32 lanes = 256 phones).
// ---------------------------------------------------------------------------
__global__ __launch_bounds__(SQ) void scan_kernel(const int* __restrict__ dur_raw) {
    __shared__ int warp_tot[8];
    __shared__ int s_is64;

    const int b    = blockIdx.x;
    const int s    = threadIdx.x;
    const int lane = s & 31;
    const int w    = s >> 5;

    if (s < 32) {
        int v = dur_raw[2 * s + 1];                     // candidate int64 high words
        unsigned m = __ballot_sync(0xffffffffu, v != 0);
        if (s == 0) s_is64 = (m == 0u) ? 1 : 0;
    }
    __syncthreads();

    int d = s_is64 ? dur_raw[(b * SQ + s) * 2]          // low word of LE int64
                   : dur_raw[b * SQ + s];

    // inclusive warp scan
    int x = d;
    #pragma unroll
    for (int off = 1; off < 32; off <<= 1) {
        int y = __shfl_up_sync(0xffffffffu, x, off);
        if (lane >= off) x += y;
    }
    if (lane == 31) warp_tot[w] = x;
    __syncthreads();

    // scan of 8 warp totals done by every thread (cheap, no extra sync)
    int base = 0;
    #pragma unroll
    for (int i = 0; i < 8; ++i)
        if (i < w) base += warp_tot[i];

    g_cum[b][s] = base + x;
}

// ---------------------------------------------------------------------------
// Kernel 2: one block per (b, s); thread c accumulates channel c over the
// phone's frame span (<= 8 frames after clamping) and 4 freq bins. Loads are
// fully coalesced (consecutive c -> consecutive addresses); 4 independent
// LDGs per iteration give MLP >= 4 to hide DRAM latency.
// ---------------------------------------------------------------------------
__global__ __launch_bounds__(CQ) void agg_kernel(const float* __restrict__ e,
                                                 float* __restrict__ out) {
    const int blk = blockIdx.x;
    const int b = blk >> 8;          // blk / SQ
    const int s = blk & (SQ - 1);    // blk % SQ
    const int c = threadIdx.x;

    int end   = g_cum[b][s];
    int start = (s == 0) ? 0 : g_cum[b][s - 1];
    start = min(start, TQ);
    end   = min(end,   TQ);
    const int cnt = end - start;

    float acc = 0.0f;
    if (cnt > 0) {
        const float* p = e + (size_t)(b * TQ + start) * (FQ * CQ) + c;
        for (int t = 0; t < cnt; ++t) {
            float a0 = p[0];
            float a1 = p[CQ];
            float a2 = p[2 * CQ];
            float a3 = p[3 * CQ];
            acc += (a0 + a1) + (a2 + a3);
            p += FQ * CQ;
        }
        acc *= 1.0f / (float)(cnt * FQ);
    }
    out[(size_t)blk * CQ + c] = acc;
}

extern "C" void kernel_launch(void* const* d_in, const int* in_sizes, int n_in,
                              void* d_out, int out_size) {
    const float* e_src = (const float*)d_in[0];   // [B, T, F, C] float32
    const int*   d_src = (const int*)d_in[1];     // [B, S] int64-or-int32 (device-detected)
    float* out = (float*)d_out;                   // [B, S, C] float32

    scan_kernel<<<BQ, SQ>>>(d_src);
    agg_kernel<<<BQ * SQ, CQ>>>(e_src, out);
}

// round 8
// speedup vs baseline: 1.1719x; 1.1719x over previous
#include <cuda_runtime.h>
#include <cuda_bf16.h>

// Problem constants: B=32, T=1024, F=4, C=256, S=256, MAX_DUR=8
#define BQ 32
#define TQ 1024
#define FQ 4
#define CQ 256
#define SQ 256
#define ROW_VEC 256   // one frame row [F=4][C=256] = 1024 floats = 256 float4

// Scratch: inclusive cumsum of durations per batch. 32*256*4B = 32 KB.
__device__ int g_cum[BQ][SQ];

// ---------------------------------------------------------------------------
// Kernel 1: per-batch inclusive scan of durations (one block per batch).
// Dtype: reference declares int64 but JAX w/o x64 downcasts to int32; detect
// on device via the high words (all zero <=> int64, P(false pos)=8^-32).
// ---------------------------------------------------------------------------
__global__ __launch_bounds__(SQ) void scan_kernel(const int* __restrict__ dur_raw) {
    __shared__ int warp_tot[8];
    __shared__ int s_is64;

    const int b    = blockIdx.x;
    const int s    = threadIdx.x;
    const int lane = s & 31;
    const int w    = s >> 5;

    if (s < 32) {
        int v = dur_raw[2 * s + 1];                     // candidate int64 high words
        unsigned m = __ballot_sync(0xffffffffu, v != 0);
        if (s == 0) s_is64 = (m == 0u) ? 1 : 0;
    }
    __syncthreads();

    int d = s_is64 ? dur_raw[(b * SQ + s) * 2]          // low word of LE int64
                   : dur_raw[b * SQ + s];

    int x = d;                                          // inclusive warp scan
    #pragma unroll
    for (int off = 1; off < 32; off <<= 1) {
        int y = __shfl_up_sync(0xffffffffu, x, off);
        if (lane >= off) x += y;
    }
    if (lane == 31) warp_tot[w] = x;
    __syncthreads();

    int base = 0;
    #pragma unroll
    for (int i = 0; i < 8; ++i)
        if (i < w) base += warp_tot[i];

    g_cum[b][s] = base + x;
}

// ---------------------------------------------------------------------------
// Kernel 2: one block per (b, s). 256 threads; thread tid loads float4 #tid
// of each frame row (a row is exactly 256 float4 covering all F and C).
// Frame loop fully unrolled to MAX_DUR=8 with predication -> 8 independent
// LDG.128 in flight per thread (MLP=8). Freq reduction via one shared pass;
// coalesced float4 output store by 64 threads.
// ---------------------------------------------------------------------------
__global__ __launch_bounds__(CQ) void agg_kernel(const float4* __restrict__ e4,
                                                 float4* __restrict__ out4) {
    __shared__ float4 sh[CQ];   // [f=4][cgroup=64]

    const int blk = blockIdx.x;
    const int b   = blk >> 8;
    const int s   = blk & (SQ - 1);
    const int tid = threadIdx.x;

    int end   = g_cum[b][s];
    int start = (s == 0) ? 0 : g_cum[b][s - 1];
    start = min(start, TQ);
    end   = min(end,   TQ);
    const int cnt = end - start;

    const float4* p = e4 + (size_t)(b * TQ + start) * ROW_VEC + tid;

    float4 acc = make_float4(0.f, 0.f, 0.f, 0.f);
    #pragma unroll
    for (int t = 0; t < 8; ++t) {
        if (t < cnt) {
            float4 v = p[t * ROW_VEC];
            acc.x += v.x; acc.y += v.y; acc.z += v.z; acc.w += v.w;
        }
    }
    sh[tid] = acc;
    __syncthreads();

    if (tid < 64) {
        float4 a = sh[tid];
        float4 b1 = sh[tid + 64];
        float4 b2 = sh[tid + 128];
        float4 b3 = sh[tid + 192];
        const float inv = (cnt > 0) ? 1.0f / (float)(cnt * FQ) : 0.0f;
        float4 r;
        r.x = ((a.x + b1.x) + (b2.x + b3.x)) * inv;
        r.y = ((a.y + b1.y) + (b2.y + b3.y)) * inv;
        r.z = ((a.z + b1.z) + (b2.z + b3.z)) * inv;
        r.w = ((a.w + b1.w) + (b2.w + b3.w)) * inv;
        out4[(size_t)blk * 64 + tid] = r;
    }
}

extern "C" void kernel_launch(void* const* d_in, const int* in_sizes, int n_in,
                              void* d_out, int out_size) {
    const float4* e_src = (const float4*)d_in[0];   // [B, T, F, C] float32
    const int*    d_src = (const int*)d_in[1];      // [B, S] int64-or-int32 (detected)
    float4* out = (float4*)d_out;                   // [B, S, C] float32

    scan_kernel<<<BQ, SQ>>>(d_src);
    agg_kernel<<<BQ * SQ, CQ>>>(e_src, out);
}